// round 7
// baseline (speedup 1.0000x reference)
#include <cuda_runtime.h>
#include <cuda_bf16.h>
#include <stdint.h>

// out[src[e]*16 + k] += attr_flat[k*E + e]
// Round-6: at the REDG-lane floor (~16M lanes). Trim everything else:
// TILE=512 @ 512 threads, direct-broadcast idx LDG (no sidx smem),
// guard-free fast path, cudaMemsetAsync zero-init.

#define TILE 512
#define VSTRIDE 516   // mult of 4 (16B rows); 516 mod 32 == 4 -> same bank math as 260

__device__ __forceinline__ uint32_t smem_u32(const void* p) {
    return (uint32_t)__cvta_generic_to_shared(p);
}
// planes 8..15: edge index XOR 8 -> scatter LDS banks land in disjoint octets
__device__ __forceinline__ int swz(int k, int el) {
    return el ^ (((k >> 3) & 1) << 3);
}

__global__ __launch_bounds__(TILE) void scatter_f16_kernel(
        const float* __restrict__ attr,
        const int* __restrict__ src_idx,
        float* __restrict__ out,
        int E) {
    __shared__ __align__(16) float vals[16][VSTRIDE]; // feature-major, swizzled

    const int t = threadIdx.x;
    const int base = blockIdx.x * TILE;
    const bool full = (base + TILE <= E);

    // ---- Fill: 2048 x 16B cp.async chunks (16 planes x 128 quads) ----
#pragma unroll
    for (int i = 0; i < 4; i++) {
        const int c  = t + TILE * i;
        const int k  = c >> 7;            // plane
        const int q4 = (c & 127) * 4;     // edge offset of this 16B chunk
        const int s4 = swz(k, q4);
        const float* gsrc = attr + (size_t)k * E + base + q4;
        uint32_t sdst = smem_u32(&vals[k][s4]);
        if (full || base + q4 + 3 < E) {
            asm volatile("cp.async.cg.shared.global [%0], [%1], 16;"
                         :: "r"(sdst), "l"(gsrc));
        } else {
            for (int j = 0; j < 4; j++)
                vals[k][s4 + j] = (base + q4 + j < E)
                                    ? attr[(size_t)k * E + base + q4 + j] : 0.f;
        }
    }
    asm volatile("cp.async.commit_group;");
    asm volatile("cp.async.wait_group 0;");
    __syncthreads();

    // ---- Scatter: lane l -> edge (l/4), feature-group (l%4) ----
    // 4 consecutive lanes cover one 64B output row -> merged wavefront.
    const int kg = t & 3;
    const int eg = t >> 2;                   // 0..127
#pragma unroll
    for (int q = 0; q < 4; q++) {
        const int el = eg + 128 * q;         // 0..511
        if (full || base + el < E) {
            // 8 consecutive ints per warp, 4 lanes each -> 1-sector broadcast LDG
            const int s = __ldg(src_idx + base + el);
            float v0 = vals[4 * kg + 0][swz(4 * kg + 0, el)];
            float v1 = vals[4 * kg + 1][swz(4 * kg + 1, el)];
            float v2 = vals[4 * kg + 2][swz(4 * kg + 2, el)];
            float v3 = vals[4 * kg + 3][swz(4 * kg + 3, el)];
            float* dst = out + (size_t)s * 16 + 4 * kg;   // 16B-aligned
            asm volatile("red.global.add.v4.f32 [%0], {%1, %2, %3, %4};"
                         :: "l"(dst), "f"(v0), "f"(v1), "f"(v2), "f"(v3)
                         : "memory");
        }
    }
}

// Generic fallback for F != 16 (scalar atomics).
__global__ void scatter_generic_kernel(const float* __restrict__ attr,
                                       const int* __restrict__ src_idx,
                                       float* __restrict__ out,
                                       int E, int F) {
    int e = blockIdx.x * blockDim.x + threadIdx.x;
    if (e >= E) return;
    const int s = src_idx[e];
    for (int k = 0; k < F; k++)
        atomicAdd(&out[(size_t)s * F + k], attr[(size_t)k * E + e]);
}

extern "C" void kernel_launch(void* const* d_in, const int* in_sizes, int n_in,
                              void* d_out, int out_size) {
    const float* attr = (const float*)d_in[0];   // (E, F) float32, flat
    const int*   idx  = (const int*)d_in[1];     // (2, E) int32; row 0 = src

    const int E = in_sizes[1] / 2;
    const int F = in_sizes[0] / E;
    float* out = (float*)d_out;

    // zero-init (harness poisons d_out); async memset is graph-capturable
    cudaMemsetAsync(out, 0, (size_t)out_size * sizeof(float), 0);

    if (F == 16) {
        int blocks = (E + TILE - 1) / TILE;
        scatter_f16_kernel<<<blocks, TILE>>>(attr, idx, out, E);
    } else {
        int blocks = (E + 255) / 256;
        scatter_generic_kernel<<<blocks, 256>>>(attr, idx, out, E, F);
    }
}

// round 9
// speedup vs baseline: 1.0245x; 1.0245x over previous
#include <cuda_runtime.h>
#include <cuda_bf16.h>
#include <stdint.h>

// out[src[e]*16 + k] += attr_flat[k*E + e]
// Round-8 consolidation: round-3 structure (edge-major smem transpose,
// LDS.128 gather, warp-coalesced red.global.add.v4.f32 — proven 62.3us
// scatter) + full-tile fast path (E divisible by TILE) + leaner zero-init.

#define TILE 256

__global__ __launch_bounds__(1024) void zero_out_kernel(float4* __restrict__ out,
                                                        int n4) {
    for (int i = blockIdx.x * blockDim.x + threadIdx.x; i < n4;
         i += gridDim.x * blockDim.x)
        out[i] = make_float4(0.f, 0.f, 0.f, 0.f);
}

__global__ __launch_bounds__(TILE) void scatter_f16_kernel(
        const float* __restrict__ attr,
        const int* __restrict__ src_idx,
        float* __restrict__ out,
        int E) {
    // Edge-major staging: row stride 20 floats (80B, 16B-aligned).
    __shared__ __align__(16) float vals[TILE][20];
    __shared__ int sidx[TILE];

    const int t = threadIdx.x;
    const int base = blockIdx.x * TILE;
    const bool full = (base + TILE <= E);     // uniform across block

    // ---- Load phase: coalesced feature-major reads, transpose via STS.128 ----
    if (full) {
        const int e = base + t;
        sidx[t] = __ldg(src_idx + e);
        float v[16];
#pragma unroll
        for (int k = 0; k < 16; k++)
            v[k] = __ldg(attr + (size_t)k * E + e);
#pragma unroll
        for (int kg = 0; kg < 4; kg++)
            *reinterpret_cast<float4*>(&vals[t][4 * kg]) =
                make_float4(v[4*kg+0], v[4*kg+1], v[4*kg+2], v[4*kg+3]);
    } else if (base + t < E) {
        const int e = base + t;
        sidx[t] = __ldg(src_idx + e);
        float v[16];
#pragma unroll
        for (int k = 0; k < 16; k++)
            v[k] = __ldg(attr + (size_t)k * E + e);
#pragma unroll
        for (int kg = 0; kg < 4; kg++)
            *reinterpret_cast<float4*>(&vals[t][4 * kg]) =
                make_float4(v[4*kg+0], v[4*kg+1], v[4*kg+2], v[4*kg+3]);
    }
    __syncthreads();

    // ---- Scatter phase: lane l -> edge (l/4), feature-group (l%4) ----
    // 4 consecutive lanes cover one contiguous 64B output row -> the warp's
    // RED.v4 merges into ~8 wavefronts instead of 32.
    const int kg = t & 3;
    const int eg = t >> 2;                 // 0..63
    if (full) {
#pragma unroll
        for (int q = 0; q < 4; q++) {
            const int el = eg + 64 * q;    // 0..255
            const int s  = sidx[el];       // 4-lane broadcast LDS
            float4 p = *reinterpret_cast<const float4*>(&vals[el][4 * kg]);
            float* dst = out + (size_t)s * 16 + 4 * kg;     // 16B-aligned
            asm volatile("red.global.add.v4.f32 [%0], {%1, %2, %3, %4};"
                         :: "l"(dst), "f"(p.x), "f"(p.y), "f"(p.z), "f"(p.w)
                         : "memory");
        }
    } else {
#pragma unroll
        for (int q = 0; q < 4; q++) {
            const int el = eg + 64 * q;
            if (base + el < E) {
                const int s = sidx[el];
                float4 p = *reinterpret_cast<const float4*>(&vals[el][4 * kg]);
                float* dst = out + (size_t)s * 16 + 4 * kg;
                asm volatile("red.global.add.v4.f32 [%0], {%1, %2, %3, %4};"
                             :: "l"(dst), "f"(p.x), "f"(p.y), "f"(p.z), "f"(p.w)
                             : "memory");
            }
        }
    }
}

// Generic fallback for F != 16 (scalar atomics).
__global__ void scatter_generic_kernel(const float* __restrict__ attr,
                                       const int* __restrict__ src_idx,
                                       float* __restrict__ out,
                                       int E, int F) {
    int e = blockIdx.x * blockDim.x + threadIdx.x;
    if (e >= E) return;
    const int s = src_idx[e];
    for (int k = 0; k < F; k++)
        atomicAdd(&out[(size_t)s * F + k], attr[(size_t)k * E + e]);
}

extern "C" void kernel_launch(void* const* d_in, const int* in_sizes, int n_in,
                              void* d_out, int out_size) {
    const float* attr = (const float*)d_in[0];   // (E, F) float32, flat
    const int*   idx  = (const int*)d_in[1];     // (2, E) int32; row 0 = src

    const int E = in_sizes[1] / 2;
    const int F = in_sizes[0] / E;
    float* out = (float*)d_out;

    {   // zero-init (harness poisons d_out)
        int n4 = out_size / 4;
        int blocks = (n4 + 1023) / 1024;
        if (blocks > 296) blocks = 296;          // ~2 waves max, grid-stride
        zero_out_kernel<<<blocks, 1024>>>((float4*)out, n4);
    }

    if (F == 16) {
        int blocks = (E + TILE - 1) / TILE;
        scatter_f16_kernel<<<blocks, TILE>>>(attr, idx, out, E);
    } else {
        int blocks = (E + 255) / 256;
        scatter_generic_kernel<<<blocks, 256>>>(attr, idx, out, E, F);
    }
}

// round 10
// speedup vs baseline: 1.1511x; 1.1236x over previous
#include <cuda_runtime.h>
#include <cuda_bf16.h>
#include <stdint.h>

// out[src[e]*16 + k] += attr_flat[k*E + e]
// Round-9 final: verbatim round-3 scatter (measured 62.3us: plain coalesced
// loads, STS/LDS.128 edge-major transpose, warp-coalesced red.global.add.v4)
// + round-8's leaner capped-grid zero-init (measured ~2.6us overhead).

#define TILE 256

__global__ __launch_bounds__(1024) void zero_out_kernel(float4* __restrict__ out,
                                                        int n4) {
    for (int i = blockIdx.x * blockDim.x + threadIdx.x; i < n4;
         i += gridDim.x * blockDim.x)
        out[i] = make_float4(0.f, 0.f, 0.f, 0.f);
}

__global__ __launch_bounds__(TILE) void scatter_f16_kernel(
        const float* __restrict__ attr,
        const int* __restrict__ src_idx,
        float* __restrict__ out,
        int E) {
    // Edge-major staging: row stride 20 floats (80B, 16B-aligned) to keep
    // STS.128 / LDS.128 (nearly) bank-conflict-free.
    __shared__ float vals[TILE][20];
    __shared__ int   sidx[TILE];

    const int t = threadIdx.x;
    const int base = blockIdx.x * TILE;
    const int e = base + t;

    // ---- Load phase: coalesced feature-major reads (1 wavefront per LDG) ----
    if (e < E) {
        sidx[t] = src_idx[e];
        float v[16];
#pragma unroll
        for (int k = 0; k < 16; k++)
            v[k] = attr[(size_t)k * E + e];
#pragma unroll
        for (int kg = 0; kg < 4; kg++) {
            float4 p = make_float4(v[4*kg+0], v[4*kg+1], v[4*kg+2], v[4*kg+3]);
            *reinterpret_cast<float4*>(&vals[t][4*kg]) = p;
        }
    }
    __syncthreads();

    // ---- Scatter phase: lane l -> edge (l/4), feature-group (l%4) ----
    // Within a warp: 8 consecutive edges x 4 contiguous 16B chunks each
    // = 8 x 64B contiguous regions -> ~8 RED wavefronts per warp-op.
    const int kg = t & 3;
    const int eg = t >> 2;           // 0..63
#pragma unroll
    for (int q = 0; q < 4; q++) {
        const int el = eg + 64 * q;  // 0..255
        if (base + el < E) {
            const int s = sidx[el];                          // 4-lane broadcast
            float4 p = *reinterpret_cast<const float4*>(&vals[el][4*kg]);
            float* dst = out + (size_t)s * 16 + 4 * kg;      // 16B-aligned
            asm volatile("red.global.add.v4.f32 [%0], {%1, %2, %3, %4};"
                         :: "l"(dst), "f"(p.x), "f"(p.y), "f"(p.z), "f"(p.w)
                         : "memory");
        }
    }
}

// Generic fallback for F != 16 (scalar atomics).
__global__ void scatter_generic_kernel(const float* __restrict__ attr,
                                       const int* __restrict__ src_idx,
                                       float* __restrict__ out,
                                       int E, int F) {
    int e = blockIdx.x * blockDim.x + threadIdx.x;
    if (e >= E) return;
    const int s = src_idx[e];
    for (int k = 0; k < F; k++)
        atomicAdd(&out[(size_t)s * F + k], attr[(size_t)k * E + e]);
}

extern "C" void kernel_launch(void* const* d_in, const int* in_sizes, int n_in,
                              void* d_out, int out_size) {
    const float* attr = (const float*)d_in[0];   // (E, F) float32, flat
    const int*   idx  = (const int*)d_in[1];     // (2, E) int32; row 0 = src

    const int E = in_sizes[1] / 2;
    const int F = in_sizes[0] / E;
    float* out = (float*)d_out;

    {   // zero-init (harness poisons d_out)
        int n4 = out_size / 4;
        int blocks = (n4 + 1023) / 1024;
        if (blocks > 296) blocks = 296;          // grid-stride, <=2 waves
        zero_out_kernel<<<blocks, 1024>>>((float4*)out, n4);
    }

    if (F == 16) {
        int blocks = (E + TILE - 1) / TILE;
        scatter_f16_kernel<<<blocks, TILE>>>(attr, idx, out, E);
    } else {
        int blocks = (E + 255) / 256;
        scatter_generic_kernel<<<blocks, 256>>>(attr, idx, out, E, F);
    }
}